// round 3
// baseline (speedup 1.0000x reference)
#include <cuda_runtime.h>
#include <cstdint>

// Problem constants (fixed by the dataset)
#define BB 32
#define TT 2048
#define DD 256
#define NCHUNK 16
#define CHUNK (TT / NCHUNK)   // 128

// Scratch: exclusive prefix sums E[b][t][d], t in [0, TT] (TT+1 rows)
__device__ float g_csum[(size_t)BB * (TT + 1) * DD];   // ~67 MB
// Per-chunk totals
__device__ float g_tot[BB * NCHUNK * DD];

// ---------------------------------------------------------------------------
// K1: per-chunk totals. grid (B, NCHUNK), block DD threads (thread = d).
// ---------------------------------------------------------------------------
__global__ void k_chunk_tot(const float* __restrict__ x) {
    const int b = blockIdx.x;
    const int c = blockIdx.y;
    const int d = threadIdx.x;
    const float* p = x + ((size_t)b * TT + (size_t)c * CHUNK) * DD + d;

    float s = 0.0f;
#pragma unroll 8
    for (int t = 0; t < CHUNK; t++) {
        s += p[(size_t)t * DD];
    }
    g_tot[(b * NCHUNK + c) * DD + d] = s;
}

// ---------------------------------------------------------------------------
// K2: write exclusive prefix sums. grid (B, NCHUNK), block DD threads.
// Each thread scans its chunk with 8-wide register prefetch (breaks the
// load->add serial chain; 8 independent loads in flight).
// ---------------------------------------------------------------------------
__global__ void k_apply_prefix(const float* __restrict__ x) {
    const int b = blockIdx.x;
    const int c = blockIdx.y;
    const int d = threadIdx.x;

    // Offset = sum of all previous chunks' totals for this (b, d)
    float off = 0.0f;
    const float* tot = g_tot + b * NCHUNK * DD + d;
    for (int i = 0; i < c; i++) off += tot[i * DD];

    const float* p = x + ((size_t)b * TT + (size_t)c * CHUNK) * DD + d;
    float* o = g_csum + ((size_t)b * (TT + 1) + (size_t)c * CHUNK) * DD + d;

    float run = off;
    for (int t0 = 0; t0 < CHUNK; t0 += 8) {
        float v[8];
#pragma unroll
        for (int i = 0; i < 8; i++) v[i] = p[(size_t)(t0 + i) * DD];
#pragma unroll
        for (int i = 0; i < 8; i++) {
            o[(size_t)(t0 + i) * DD] = run;
            run += v[i];
        }
    }
    // last chunk also writes E[TT] (the total)
    if (c == NCHUNK - 1) {
        o[(size_t)CHUNK * DD] = run;
    }
}

// ---------------------------------------------------------------------------
// K3: per-pair span means. 256 threads/block = 4 pairs/block, 64 threads/pair,
// each thread handles one float4 (4 d's). Reads: 4 coalesced 1KB rows from
// L2-resident g_csum. Writes: streaming (__stcs) 2KB per pair to d_out.
// ---------------------------------------------------------------------------
__global__ void k_pairs(const int* __restrict__ p1_start,
                        const int* __restrict__ p1_span,
                        const int* __restrict__ p2_start,
                        const int* __restrict__ p2_span,
                        const int* __restrict__ pair_batch,
                        float* __restrict__ out,
                        int P) {
    const int pair = blockIdx.x * 4 + (threadIdx.x >> 6);
    if (pair >= P) return;
    const int lane = threadIdx.x & 63;   // float4 index within D=256 (64 x 4)

    const int b = pair_batch[pair];
    const float4* base =
        reinterpret_cast<const float4*>(g_csum) + (size_t)b * (TT + 1) * (DD / 4) + lane;

    float4* orow = reinterpret_cast<float4*>(out) + (size_t)pair * (2 * DD / 4);

    // ---- side 1 ----
    {
        const int a = p1_start[pair];
        const int n = p1_span[pair];
        const float inv = 1.0f / (float)n;
        float4 hi = __ldg(&base[(size_t)(a + n) * (DD / 4)]);
        float4 lo = __ldg(&base[(size_t)a * (DD / 4)]);
        float4 r;
        r.x = (hi.x - lo.x) * inv;
        r.y = (hi.y - lo.y) * inv;
        r.z = (hi.z - lo.z) * inv;
        r.w = (hi.w - lo.w) * inv;
        __stcs(&orow[lane], r);
    }
    // ---- side 2 ----
    {
        const int a = p2_start[pair];
        const int n = p2_span[pair];
        const float inv = 1.0f / (float)n;
        float4 hi = __ldg(&base[(size_t)(a + n) * (DD / 4)]);
        float4 lo = __ldg(&base[(size_t)a * (DD / 4)]);
        float4 r;
        r.x = (hi.x - lo.x) * inv;
        r.y = (hi.y - lo.y) * inv;
        r.z = (hi.z - lo.z) * inv;
        r.w = (hi.w - lo.w) * inv;
        __stcs(&orow[(DD / 4) + lane], r);
    }
}

// ---------------------------------------------------------------------------
extern "C" void kernel_launch(void* const* d_in, const int* in_sizes, int n_in,
                              void* d_out, int out_size) {
    const float* token_embs = (const float*)d_in[0];
    const int* p1_start = (const int*)d_in[1];
    const int* p1_span  = (const int*)d_in[2];
    const int* p2_start = (const int*)d_in[3];
    const int* p2_span  = (const int*)d_in[4];
    const int* pair_batch = (const int*)d_in[5];
    float* out = (float*)d_out;

    const int P = in_sizes[1];   // number of pairs

    dim3 gridA(BB, NCHUNK);
    k_chunk_tot<<<gridA, DD>>>(token_embs);
    k_apply_prefix<<<gridA, DD>>>(token_embs);

    const int pairs_per_block = 4;
    const int gridP = (P + pairs_per_block - 1) / pairs_per_block;
    k_pairs<<<gridP, 256>>>(p1_start, p1_span, p2_start, p2_span, pair_batch,
                            out, P);
}

// round 4
// speedup vs baseline: 1.1345x; 1.1345x over previous
#include <cuda_runtime.h>
#include <cstdint>

// Problem constants (fixed by the dataset)
#define BB 32
#define TT 2048
#define DD 256
#define D4 (DD / 4)            // 64 float4 lanes per row
#define NCHUNK 16
#define CHUNK (TT / NCHUNK)    // 128 rows per chunk
#define TPG 16                 // t-rows per thread
#define NGRP (CHUNK / TPG)     // 8 groups per block
#define SCAN_THREADS (D4 * NGRP)  // 512

// Scratch: exclusive prefix sums E[b][t][d], t in [0, TT]
__device__ float g_csum[(size_t)BB * (TT + 1) * DD];   // ~67 MB
// Per-chunk aggregate vectors (one float4 per lane)
__device__ float4 g_ctot[BB * NCHUNK * D4];
// Publish flags (zero-initialized; reset each replay by k_pairs block 0)
__device__ int g_flag[BB * NCHUNK];

// ---------------------------------------------------------------------------
// Single-pass scan with decoupled lookback (aggregate style, no serial chain).
// grid = BB*NCHUNK blocks; bid = b*NCHUNK + c so predecessors (same b,
// smaller c) have smaller blockIdx -> scheduled no later than us.
// Each thread: lane = float4 column, grp = which 16-row slab of the chunk.
// Data held in registers between the "sum" and "write prefixes" phases, so
// the input is read from DRAM exactly once.
// ---------------------------------------------------------------------------
__global__ __launch_bounds__(SCAN_THREADS, 1)
void k_scan(const float* __restrict__ x) {
    __shared__ float4 s_tot[NGRP][D4];   // per-group totals
    __shared__ float4 s_off[D4];         // chunk offset vector (from lookback)

    const int bid  = blockIdx.x;
    const int c    = bid & (NCHUNK - 1);
    const int b    = bid >> 4;
    const int lane = threadIdx.x & (D4 - 1);
    const int grp  = threadIdx.x >> 6;

    const int t0 = c * CHUNK + grp * TPG;
    const float4* x4 = reinterpret_cast<const float4*>(x)
                       + ((size_t)b * TT + t0) * D4 + lane;

    // ---- Phase 1: load 16 rows into registers, compute this thread's total
    float4 v[TPG];
#pragma unroll
    for (int i = 0; i < TPG; i++) v[i] = x4[(size_t)i * D4];

    float4 tot = v[0];
#pragma unroll
    for (int i = 1; i < TPG; i++) {
        tot.x += v[i].x; tot.y += v[i].y; tot.z += v[i].z; tot.w += v[i].w;
    }
    s_tot[grp][lane] = tot;
    __syncthreads();

    // ---- Per-thread offset within the chunk (sum of previous groups)
    float4 goff = make_float4(0.f, 0.f, 0.f, 0.f);
    for (int g = 0; g < grp; g++) {
        float4 t2 = s_tot[g][lane];
        goff.x += t2.x; goff.y += t2.y; goff.z += t2.z; goff.w += t2.w;
    }

    // ---- Publish this chunk's aggregate (last group holds chunk total)
    if (grp == NGRP - 1) {
        float4 ct;
        ct.x = goff.x + tot.x; ct.y = goff.y + tot.y;
        ct.z = goff.z + tot.z; ct.w = goff.w + tot.w;
        g_ctot[bid * D4 + lane] = ct;
    }
    __syncthreads();                      // all aggregate stores issued + block-visible
    if (threadIdx.x == (NGRP - 1) * D4) {
        __threadfence();                  // make aggregates device-visible
        atomicExch(&g_flag[bid], 1);      // release
    }

    // ---- Lookback: sum all predecessor aggregates (independent, no chain)
    float4 choff = make_float4(0.f, 0.f, 0.f, 0.f);
    if (c > 0) {
        if ((int)threadIdx.x < c) {
            volatile int* fl = g_flag + b * NCHUNK + threadIdx.x;
            while (*fl == 0) { }
        }
        __syncthreads();
        __threadfence();                  // acquire before reading aggregates
        if (grp == 0) {
            float4 co = make_float4(0.f, 0.f, 0.f, 0.f);
            for (int j = 0; j < c; j++) {
                float4 t2 = g_ctot[(b * NCHUNK + j) * D4 + lane];
                co.x += t2.x; co.y += t2.y; co.z += t2.z; co.w += t2.w;
            }
            s_off[lane] = co;
        }
        __syncthreads();
        choff = s_off[lane];
    }

    // ---- Phase 2: write exclusive prefixes from registers
    float4 run;
    run.x = choff.x + goff.x; run.y = choff.y + goff.y;
    run.z = choff.z + goff.z; run.w = choff.w + goff.w;

    float4* o4 = reinterpret_cast<float4*>(g_csum)
                 + ((size_t)b * (TT + 1) + t0) * D4 + lane;
#pragma unroll
    for (int i = 0; i < TPG; i++) {
        o4[(size_t)i * D4] = run;
        run.x += v[i].x; run.y += v[i].y; run.z += v[i].z; run.w += v[i].w;
    }
    if (c == NCHUNK - 1 && grp == NGRP - 1) {
        o4[(size_t)TPG * D4] = run;       // row TT (inclusive total)
    }
}

// ---------------------------------------------------------------------------
// K3: per-pair span means. 256 threads/block = 4 pairs/block, 64 threads/pair,
// one float4 per thread per side. All 4 csum loads issued before arithmetic
// (MLP=4). Streaming stores for output (don't evict csum from L2).
// Block 0 also resets the scan flags for the next graph replay (the scan
// kernel of the next replay runs strictly after this kernel in stream order).
// ---------------------------------------------------------------------------
__global__ void k_pairs(const int* __restrict__ p1_start,
                        const int* __restrict__ p1_span,
                        const int* __restrict__ p2_start,
                        const int* __restrict__ p2_span,
                        const int* __restrict__ pair_batch,
                        float* __restrict__ out,
                        int P) {
    if (blockIdx.x == 0 && threadIdx.x < BB * NCHUNK) {
        g_flag[threadIdx.x] = 0;
    }

    const int pair = blockIdx.x * 4 + (threadIdx.x >> 6);
    if (pair >= P) return;
    const int lane = threadIdx.x & 63;

    const int b  = pair_batch[pair];
    const int a1 = p1_start[pair];
    const int n1 = p1_span[pair];
    const int a2 = p2_start[pair];
    const int n2 = p2_span[pair];

    const float4* base =
        reinterpret_cast<const float4*>(g_csum) + (size_t)b * (TT + 1) * D4 + lane;

    float4 hi1 = __ldg(&base[(size_t)(a1 + n1) * D4]);
    float4 lo1 = __ldg(&base[(size_t)a1 * D4]);
    float4 hi2 = __ldg(&base[(size_t)(a2 + n2) * D4]);
    float4 lo2 = __ldg(&base[(size_t)a2 * D4]);

    const float inv1 = 1.0f / (float)n1;
    const float inv2 = 1.0f / (float)n2;

    float4 r1;
    r1.x = (hi1.x - lo1.x) * inv1;
    r1.y = (hi1.y - lo1.y) * inv1;
    r1.z = (hi1.z - lo1.z) * inv1;
    r1.w = (hi1.w - lo1.w) * inv1;

    float4 r2;
    r2.x = (hi2.x - lo2.x) * inv2;
    r2.y = (hi2.y - lo2.y) * inv2;
    r2.z = (hi2.z - lo2.z) * inv2;
    r2.w = (hi2.w - lo2.w) * inv2;

    float4* orow = reinterpret_cast<float4*>(out) + (size_t)pair * (2 * D4);
    __stcs(&orow[lane], r1);
    __stcs(&orow[D4 + lane], r2);
}

// ---------------------------------------------------------------------------
extern "C" void kernel_launch(void* const* d_in, const int* in_sizes, int n_in,
                              void* d_out, int out_size) {
    const float* token_embs = (const float*)d_in[0];
    const int* p1_start   = (const int*)d_in[1];
    const int* p1_span    = (const int*)d_in[2];
    const int* p2_start   = (const int*)d_in[3];
    const int* p2_span    = (const int*)d_in[4];
    const int* pair_batch = (const int*)d_in[5];
    float* out = (float*)d_out;

    const int P = in_sizes[1];

    k_scan<<<BB * NCHUNK, SCAN_THREADS>>>(token_embs);

    const int gridP = (P + 3) / 4;
    k_pairs<<<gridP, 256>>>(p1_start, p1_span, p2_start, p2_span, pair_batch,
                            out, P);
}